// round 16
// baseline (speedup 1.0000x reference)
#include <cuda_runtime.h>
#include <cuda_bf16.h>

// Problem constants (fixed by the reference)
#define BATCH   2
#define NPTS    8192
#define NTOT    (BATCH * NPTS)
#define DIM     32
#define R2      0.0009f     // 0.03^2
#define SIMT    0.7f
#define EPSN    1e-8f
#define MINLEAF 10

#define GRIDC   14                      // ceil(0.4 / 0.03)
#define NCELL   (GRIDC * GRIDC * GRIDC) // 2744
#define CAP     32                      // bucket capacity (mean occupancy ~1.5)
#define INVC    33.333332f              // 1 / 0.03
#define MARGIN  0.0302f                 // radius + safety margin for cell-range bound

#define TPB     256
#define NB      512                     // 16384 points / 32 per block
#define LPP     16                      // lanes per point (query)
#define PPB2    32                      // points per block
#define FULL    0xffffffffu
#define PAD     32                      // row stride (row-parallel access: conflict-free)
#define CCAP    64                      // per-point d2-pass candidate capacity
#define LCAP    32                      // per-point sim-pass list capacity

// Scratch (static __device__ — no allocations allowed)
__device__ float  g_en[NTOT * DIM];                  // normalized embeddings
__device__ int    g_cellcnt[BATCH * NCELL];
__device__ float4 g_bucket[BATCH * NCELL * CAP];     // (x,y,z, bitcast local idx)
__device__ int    g_leafcnt[BATCH];
__device__ int    g_bar_arrive;                      // zero-initialized
__device__ volatile int g_bar_gen;                   // monotonic epoch (never reset)

// Sense-reversal grid barrier. Safe: NB=512 <= 148 SMs x 4 co-resident blocks
// (regs<=64 via launch_bounds(256,4); smem ~38KB*4 <= 228KB).
__device__ __forceinline__ void grid_barrier() {
    __syncthreads();
    if (threadIdx.x == 0) {
        int gen = g_bar_gen;
        __threadfence();
        if (atomicAdd(&g_bar_arrive, 1) == NB - 1) {
            atomicExch(&g_bar_arrive, 0);
            __threadfence();
            g_bar_gen = gen + 1;                     // release
        } else {
            while (g_bar_gen == gen) { __nanosleep(20); }
        }
        __threadfence();
    }
    __syncthreads();
}

__global__ void __launch_bounds__(TPB, 4)
fused_kernel(const float* __restrict__ points,
             const float* __restrict__ emb,
             const int*   __restrict__ leaf,
             const float* __restrict__ W1,
             const float* __restrict__ b1,
             const float* __restrict__ W2,
             const float* __restrict__ b2,
             float* __restrict__ out) {
    __shared__ __align__(16) float sW1[2 * DIM * DIM];   // 8 KB
    __shared__ __align__(16) float sW2[DIM * DIM];       // 4 KB
    __shared__ float sb1[DIM];
    __shared__ float sb2[DIM];
    __shared__ unsigned char s_cnt8[BATCH * NCELL];      // 5.4 KB (clamped u8 counts)
    __shared__ __align__(16) float s_en[PPB2 * PAD];     // normalized emb, 32 points (4 KB)
    __shared__ __align__(16) float s_ei[PPB2 * PAD];     // raw emb, 32 points (4 KB)
    __shared__ int   s_cand[PPB2 * CCAP];                // d2-pass candidate lists (8 KB)
    __shared__ int   s_ccnt[PPB2];                       // candidate counters (== nbcnt)
    __shared__ int   s_list[PPB2 * LCAP];                // sim-pass j lists (4 KB)
    __shared__ int   s_lcnt[PPB2];                       // sim-pass counters (== cnt)

    const int tid  = threadIdx.x;
    const int bblk = (blockIdx.x * PPB2) >> 13;          // block-uniform batch

    // ---- stage weights (no deps; overlaps everything below) ----
    for (int t = tid; t < 2 * DIM * DIM; t += TPB) sW1[t] = W1[t];
    for (int t = tid; t < DIM * DIM; t += TPB)     sW2[t] = W2[t];
    if (tid < DIM) { sb1[tid] = b1[tid]; sb2[tid] = b2[tid]; }

    // ---- Phase Z slice: zero grid state ----
    {
        const int gtid = blockIdx.x * TPB + tid;
        if (gtid < BATCH * NCELL) g_cellcnt[gtid] = 0;
        if (gtid < BATCH)         g_leafcnt[gtid] = 0;
    }

    // ---- Prep-normalize BEFORE barrier 1 (overlaps other blocks' Z waits).
    //      8 threads per point: parallel emb loads; norm by sub-lane 0 from
    //      smem in the EXACT sequential order (bit-identical inv). ----
    const int sp  = tid >> 3;                            // 0..31 point slot
    const int sub = tid & 7;                             // 0..7  sub-lane
    const int gp  = blockIdx.x * PPB2 + sp;              // this thread's prep point
    {
        float4 t = __ldg((const float4*)(emb + (size_t)gp * DIM) + sub);
        ((float4*)(s_ei + sp * PAD))[sub] = t;
        __syncwarp();
        float inv = 0.f;
        if (sub == 0) {
            const float4* row = (const float4*)(s_ei + sp * PAD);
            float s = 0.f;
#pragma unroll
            for (int q = 0; q < 8; q++) {
                float4 u = row[q];
                s = fmaf(u.x, u.x, s); s = fmaf(u.y, u.y, s);
                s = fmaf(u.z, u.z, s); s = fmaf(u.w, u.w, s);
            }
            inv = 1.f / fmaxf(sqrtf(s), EPSN);
        }
        inv = __shfl_sync(FULL, inv, (tid & 31) & ~7, 32);   // broadcast within 8-group
        float4 o = make_float4(t.x * inv, t.y * inv, t.z * inv, t.w * inv);
        ((float4*)(s_en + sp * PAD))[sub] = o;
        ((float4*)(g_en + (size_t)gp * DIM))[sub] = o;
    }
    grid_barrier();                                      // zeros visible everywhere

    // ---- grid insert + leaf count (tiny; sub-lane 0 per point) ----
    {
        int lf = 0;
        if (sub == 0) lf = (leaf[gp] > 0);
        unsigned msk = __ballot_sync(FULL, (sub == 0) && lf);
        if ((tid & 31) == 0 && msk)
            atomicAdd(&g_leafcnt[bblk], __popc(msk));
        if ((sub == 0) && lf) {
            float x = points[3 * (size_t)gp];
            float y = points[3 * (size_t)gp + 1];
            float z = points[3 * (size_t)gp + 2];
            int cx = min(GRIDC - 1, (int)(x * INVC));
            int cy = min(GRIDC - 1, (int)(y * INVC));
            int cz = min(GRIDC - 1, (int)(z * INVC));
            int c = bblk * NCELL + (cz * GRIDC + cy) * GRIDC + cx;
            int pos = atomicAdd(&g_cellcnt[c], 1);
            if (pos < CAP)
                g_bucket[(size_t)c * CAP + pos] =
                    make_float4(x, y, z, __int_as_float(gp - bblk * NPTS));
        }
    }
    grid_barrier();                                      // buckets complete

    // ---- Phase Q setup ----
    for (int t = tid; t < BATCH * NCELL; t += TPB)
        s_cnt8[t] = (unsigned char)min(g_cellcnt[t], CAP);
    if (tid < PPB2) { s_ccnt[tid] = 0; s_lcnt[tid] = 0; }
    __syncthreads();                                     // the ONLY Phase-Q block sync

    const int lcb = g_leafcnt[bblk];
    const int ln = tid & 15;                             // lane within point group
    const int pg = tid >> 4;                             // 0..15 group id in block
    const unsigned gmask = 0xFFFFu << (tid & 16);        // this group's 16 lanes
    const float* enb  = g_en + (size_t)bblk * NPTS * DIM;
    const float* embb = emb  + (size_t)bblk * NPTS * DIM;
    const unsigned char* cntb = s_cnt8 + bblk * NCELL;

#pragma unroll
    for (int w = 0; w < 2; w++) {
        const int spq = w * 16 + pg;                     // point slot (0..31)
        const int gi = blockIdx.x * PPB2 + spq;          // global point id
        const float* en_i = s_en + spq * PAD;

        const float xi = __ldg(points + 3 * (size_t)gi);
        const float yi = __ldg(points + 3 * (size_t)gi + 1);
        const float zi = __ldg(points + 3 * (size_t)gi + 2);

        const int cx0 = max(0, (int)((xi - MARGIN) * INVC)), cx1 = min(GRIDC - 1, (int)((xi + MARGIN) * INVC));
        const int cy0 = max(0, (int)((yi - MARGIN) * INVC)), cy1 = min(GRIDC - 1, (int)((yi + MARGIN) * INVC));
        const int cz0 = max(0, (int)((zi - MARGIN) * INVC)), cz1 = min(GRIDC - 1, (int)((zi + MARGIN) * INVC));
        const int nx = cx1 - cx0 + 1, ny = cy1 - cy0 + 1, nz = cz1 - cz0 + 1;
        const int nxy = nx * ny, ncn = nxy * nz;         // <= 64
        const float invnxy = 1.f / (float)nxy;
        const float invnx  = 1.f / (float)nx;

        // ---- Phase A: geometric scan; pair-load slots 0,1 (one L2 round trip
        //      for ~80% of nonempty cells); candidate order per lane unchanged ----
#pragma unroll
        for (int s = 0; s < 64 / LPP; s++) {             // 4 iters; lane owns cc
            int cc = ln + s * LPP;
            if (cc < ncn) {
                // division-free decode: exact for cc<64
                int cz = (int)(((float)cc + 0.5f) * invnxy);
                int r  = cc - cz * nxy;
                int cy = (int)(((float)r + 0.5f) * invnx);
                int cx = r - cy * nx;
                int cell = ((cz0 + cz) * GRIDC + (cy0 + cy)) * GRIDC + (cx0 + cx);
                int n = cntb[cell];                      // already clamped to CAP
                if (n > 0) {
                    const float4* bk = g_bucket + ((size_t)bblk * NCELL + cell) * CAP;
                    float4 p0 = __ldg(bk);               // slot 0
                    if (n > 1) {
                        float4 p1 = __ldg(bk + 1);       // slot 1: issued before p0 use
                        {
                            float dx = xi - p0.x, dy = yi - p0.y, dz = zi - p0.z;
                            float d2 = fmaf(dx, dx, fmaf(dy, dy, dz * dz));
                            if (d2 < R2) {
                                int pos = atomicAdd(&s_ccnt[spq], 1);
                                if (pos < CCAP) s_cand[spq * CCAP + pos] = __float_as_int(p0.w);
                            }
                        }
                        {
                            float dx = xi - p1.x, dy = yi - p1.y, dz = zi - p1.z;
                            float d2 = fmaf(dx, dx, fmaf(dy, dy, dz * dz));
                            if (d2 < R2) {
                                int pos = atomicAdd(&s_ccnt[spq], 1);
                                if (pos < CCAP) s_cand[spq * CCAP + pos] = __float_as_int(p1.w);
                            }
                        }
                        for (int k = 2; k < n; k++) {    // rare tail
                            float4 p = __ldg(bk + k);
                            float dx = xi - p.x, dy = yi - p.y, dz = zi - p.z;
                            float d2 = fmaf(dx, dx, fmaf(dy, dy, dz * dz));
                            if (d2 < R2) {
                                int pos = atomicAdd(&s_ccnt[spq], 1);
                                if (pos < CCAP) s_cand[spq * CCAP + pos] = __float_as_int(p.w);
                            }
                        }
                    } else {
                        float dx = xi - p0.x, dy = yi - p0.y, dz = zi - p0.z;
                        float d2 = fmaf(dx, dx, fmaf(dy, dy, dz * dz));
                        if (d2 < R2) {
                            int pos = atomicAdd(&s_ccnt[spq], 1);
                            if (pos < CCAP) s_cand[spq * CCAP + pos] = __float_as_int(p0.w);
                        }
                    }
                }
            }
        }
        __syncwarp();                                    // candidate lists visible

        // ---- Phase B: dots computed cooperatively (full SIMT efficiency) ----
        const int nbcnt = s_ccnt[spq];                   // exact count (pre-clamp)
        const int mcand = min(nbcnt, CCAP);
        for (int i = ln; i < mcand; i += LPP) {          // lane takes candidate i
            int j = s_cand[spq * CCAP + i];
            const float4* ej = (const float4*)(enb + (size_t)j * DIM);
            float dot = 0.f;
#pragma unroll
            for (int q = 0; q < 8; q++) {
                float4 v = __ldg(ej + q);
                float4 u = *(const float4*)(en_i + 4 * q);   // broadcast LDS.128
                dot = fmaf(v.x, u.x, dot); dot = fmaf(v.y, u.y, dot);
                dot = fmaf(v.z, u.z, dot); dot = fmaf(v.w, u.w, dot);
            }
            if (dot > SIMT) {                            // rare: defer j
                int pos = atomicAdd(&s_lcnt[spq], 1);
                if (pos < LCAP) s_list[spq * LCAP + pos] = j;
            }
        }
        __syncwarp();                                    // sim lists visible

        const int cnt = s_lcnt[spq];                     // group-uniform
        const bool cond = (__ldg(leaf + gi) > 0) && (nbcnt > 1) && (cnt > 0)
                       && (lcb >= MINLEAF);

        const int ob = ln * 2;
        if (cond) {                                      // group-uniform branch
            const float rinv = 1.f / (float)cnt;         // cnt>0 here: == max(cnt,1)

            // cooperative accumulate: lane owns components {2ln, 2ln+1}
            float acc0 = 0.f, acc1 = 0.f;
            const int mm = min(cnt, LCAP);
            for (int i = 0; i < mm; i++) {
                int jj = s_list[spq * LCAP + i];         // broadcast LDS
                float2 v = *(const float2*)(embb + (size_t)jj * DIM + ob);  // 128B coalesced
                acc0 += v.x; acc1 += v.y;                // RAW embedding (exact)
            }
            const float cA = acc0 * rinv, cB = acc1 * rinv;

            float h0 = sb1[ob], h1 = sb1[ob + 1];
#pragma unroll 8
            for (int k = 0; k < DIM; k++) {
                float c = s_ei[spq * PAD + k];
                float2 wv = *(const float2*)(sW1 + k * DIM + ob);
                h0 = fmaf(c, wv.x, h0); h1 = fmaf(c, wv.y, h1);
            }
            // second half: acc broadcast via width-16 shfl, k ascending (same order)
#pragma unroll 8
            for (int k16 = 0; k16 < 16; k16++) {
                float c0 = __shfl_sync(gmask, cA, k16, 16);   // mean_sim[2*k16]
                float c1 = __shfl_sync(gmask, cB, k16, 16);   // mean_sim[2*k16+1]
                float2 w0 = *(const float2*)(sW1 + (DIM + 2 * k16) * DIM + ob);
                h0 = fmaf(c0, w0.x, h0); h1 = fmaf(c0, w0.y, h1);
                float2 w1 = *(const float2*)(sW1 + (DIM + 2 * k16 + 1) * DIM + ob);
                h0 = fmaf(c1, w1.x, h0); h1 = fmaf(c1, w1.y, h1);
            }
            h0 = fmaxf(h0, 0.f); h1 = fmaxf(h1, 0.f);

            // layer 2: h broadcast via width-16 shfl (group-converged: cond uniform)
            float o0 = sb2[ob], o1 = sb2[ob + 1];
#pragma unroll 8
            for (int k16 = 0; k16 < 16; k16++) {
                float c0 = __shfl_sync(gmask, h0, k16, 16);   // h[2*k16]
                float c1 = __shfl_sync(gmask, h1, k16, 16);   // h[2*k16+1]
                float2 w0 = *(const float2*)(sW2 + (2 * k16) * DIM + ob);
                o0 = fmaf(c0, w0.x, o0); o1 = fmaf(c0, w0.y, o1);
                float2 w1 = *(const float2*)(sW2 + (2 * k16 + 1) * DIM + ob);
                o0 = fmaf(c1, w1.x, o0); o1 = fmaf(c1, w1.y, o1);
            }
            *(float2*)(out + (size_t)gi * DIM + ob) = make_float2(o0, o1);
        } else {
            float2 r = *(const float2*)(s_ei + spq * PAD + ob);   // passthrough
            *(float2*)(out + (size_t)gi * DIM + ob) = r;
        }
        // no block sync: slots are per-point, staged once
    }
}

extern "C" void kernel_launch(void* const* d_in, const int* in_sizes, int n_in,
                              void* d_out, int out_size) {
    const float* points = (const float*)d_in[0];
    const float* emb    = (const float*)d_in[1];
    const int*   leaf   = (const int*)d_in[2];
    const float* W1     = (const float*)d_in[3];
    const float* b1     = (const float*)d_in[4];
    const float* W2     = (const float*)d_in[5];
    const float* b2     = (const float*)d_in[6];
    float* out = (float*)d_out;

    fused_kernel<<<NB, TPB>>>(points, emb, leaf, W1, b1, W2, b2, out);
}

// round 17
// speedup vs baseline: 1.4941x; 1.4941x over previous
#include <cuda_runtime.h>
#include <cuda_bf16.h>

// Problem constants (fixed by the reference)
#define BATCH   2
#define NPTS    8192
#define NTOT    (BATCH * NPTS)
#define DIM     32
#define R2      0.0009f     // 0.03^2
#define SIMT    0.7f
#define EPSN    1e-8f
#define MINLEAF 10

#define GRIDC   14                      // ceil(0.4 / 0.03)
#define NCELL   (GRIDC * GRIDC * GRIDC) // 2744
#define CAP     32                      // bucket capacity (mean occupancy ~1.5)
#define INVC    33.333332f              // 1 / 0.03
#define MARGIN  0.0302f                 // radius + safety margin for cell-range bound

#define TPB     256
#define NB      512                     // 1024 tiles / 512 blocks = exactly 2 each
#define LPP     16                      // lanes per point
#define PPB2    32                      // points per block (both tiles merged)
#define FULL    0xffffffffu
#define PAD     32                      // row stride (row-parallel access: conflict-free)
#define CCAP    64                      // per-point d2-pass candidate capacity
#define LCAP    32                      // per-point sim-pass list capacity

// Scratch (static __device__ — no allocations allowed)
__device__ float  g_en[NTOT * DIM];                  // normalized embeddings
__device__ int    g_cellcnt[BATCH * NCELL];
__device__ float4 g_bucket[BATCH * NCELL * CAP];     // (x,y,z, bitcast local idx)
__device__ int    g_leafcnt[BATCH];
__device__ int    g_bar_arrive;                      // zero-initialized
__device__ volatile int g_bar_gen;                   // monotonic epoch (never reset)

// Sense-reversal grid barrier. Safe: NB=512 <= 148 SMs x 4 co-resident blocks
// (regs<=64 via launch_bounds(256,4); smem ~39KB*4 <= 228KB).
__device__ __forceinline__ void grid_barrier() {
    __syncthreads();
    if (threadIdx.x == 0) {
        int gen = g_bar_gen;
        __threadfence();
        if (atomicAdd(&g_bar_arrive, 1) == NB - 1) {
            atomicExch(&g_bar_arrive, 0);
            __threadfence();
            g_bar_gen = gen + 1;                     // release
        } else {
            while (g_bar_gen == gen) { __nanosleep(20); }
        }
        __threadfence();
    }
    __syncthreads();
}

__global__ void __launch_bounds__(TPB, 4)
fused_kernel(const float* __restrict__ points,
             const float* __restrict__ emb,
             const int*   __restrict__ leaf,
             const float* __restrict__ W1,
             const float* __restrict__ b1,
             const float* __restrict__ W2,
             const float* __restrict__ b2,
             float* __restrict__ out) {
    __shared__ __align__(16) float sW1[2 * DIM * DIM];   // 8 KB
    __shared__ __align__(16) float sW2[DIM * DIM];       // 4 KB
    __shared__ float sb1[DIM];
    __shared__ float sb2[DIM];
    __shared__ unsigned char s_cnt8[BATCH * NCELL];      // 5.4 KB (clamped u8 counts)
    __shared__ __align__(16) float s_en[PPB2 * PAD];     // normalized emb, 32 points (4 KB)
    __shared__ __align__(16) float s_ei[PPB2 * PAD];     // raw emb, 32 points (4 KB)
    __shared__ int   s_cand[PPB2 * CCAP];                // d2-pass candidate lists (8 KB)
    __shared__ int   s_ccnt[PPB2];                       // candidate counters (== nbcnt)
    __shared__ int   s_list[PPB2 * LCAP];                // sim-pass j lists (4 KB)
    __shared__ int   s_lcnt[PPB2];                       // sim-pass counters (== cnt)

    const int tid = threadIdx.x;

    // ---- stage weights first: L2 latency hides under the barrier waits ----
    for (int t = tid; t < 2 * DIM * DIM; t += TPB) sW1[t] = W1[t];
    for (int t = tid; t < DIM * DIM; t += TPB)     sW2[t] = W2[t];
    if (tid < DIM) { sb1[tid] = b1[tid]; sb2[tid] = b2[tid]; }

    // ---- Phase Z: zero grid state ----
    {
        const int gtid = blockIdx.x * TPB + tid;
        if (gtid < BATCH * NCELL) g_cellcnt[gtid] = 0;
        if (gtid < BATCH)         g_leafcnt[gtid] = 0;
    }
    grid_barrier();

    // ---- Phase P: prep, 32 items per block (16384 = 512*32), 1 item/lane ----
    if (tid < 32) {
        const int idx = blockIdx.x * 32 + tid;           // warp 0 fully active
        const int b = idx / NPTS;                        // warp-homogeneous
        const int j = idx - b * NPTS;

        const float4* e4 = (const float4*)(emb + (size_t)idx * DIM);
        float v[DIM];
        float s = 0.f;
#pragma unroll
        for (int q = 0; q < 8; q++) {
            float4 t = __ldg(e4 + q);
            v[4*q+0] = t.x; v[4*q+1] = t.y; v[4*q+2] = t.z; v[4*q+3] = t.w;
            s = fmaf(t.x, t.x, s); s = fmaf(t.y, t.y, s);
            s = fmaf(t.z, t.z, s); s = fmaf(t.w, t.w, s);
        }
        float inv = 1.f / fmaxf(sqrtf(s), EPSN);
        float4* o4 = (float4*)(g_en + (size_t)idx * DIM);
#pragma unroll
        for (int q = 0; q < 8; q++)
            o4[q] = make_float4(v[4*q] * inv, v[4*q+1] * inv, v[4*q+2] * inv, v[4*q+3] * inv);

        int lf = leaf[idx] > 0;
        unsigned msk = __ballot_sync(FULL, lf);
        if (tid == 0 && msk)
            atomicAdd(&g_leafcnt[b], __popc(msk));

        if (lf) {
            float x = points[3 * (size_t)idx];
            float y = points[3 * (size_t)idx + 1];
            float z = points[3 * (size_t)idx + 2];
            int cx = min(GRIDC - 1, (int)(x * INVC));
            int cy = min(GRIDC - 1, (int)(y * INVC));
            int cz = min(GRIDC - 1, (int)(z * INVC));
            int c = b * NCELL + (cz * GRIDC + cy) * GRIDC + cx;
            int pos = atomicAdd(&g_cellcnt[c], 1);
            if (pos < CAP)
                g_bucket[(size_t)c * CAP + pos] = make_float4(x, y, z, __int_as_float(j));
        }
    }
    grid_barrier();

    // ---- Phase Q: single cooperative stage of BOTH tiles (32 points), then
    //      each warp runs its points to completion with no block syncs ----
    for (int t = tid; t < BATCH * NCELL; t += TPB)
        s_cnt8[t] = (unsigned char)min(g_cellcnt[t], CAP);
    for (int t = tid; t < PPB2 * DIM; t += TPB) {
        int sp = t >> 5, k = t & 31;                     // sp: 0..31 point slot
        int w  = sp >> 4, p = sp & 15;                   // tile half, local point
        int gp = (blockIdx.x + w * NB) * LPP + p;        // global point id
        s_ei[sp * PAD + k] = __ldg(emb + (size_t)gp * DIM + k);
        s_en[sp * PAD + k] = g_en[(size_t)gp * DIM + k];
    }
    if (tid < PPB2) { s_ccnt[tid] = 0; s_lcnt[tid] = 0; }
    __syncthreads();                                     // the ONLY Phase-Q block sync

    const int lc0 = g_leafcnt[0], lc1 = g_leafcnt[1];
    const int ln = tid & 15;                             // lane within point group
    const int pg = tid >> 4;                             // 0..15 group id in block
    const unsigned gmask = 0xFFFFu << (tid & 16);        // this group's 16 lanes

#pragma unroll
    for (int w = 0; w < 2; w++) {
        const int sp = w * 16 + pg;                      // point slot (0..31)
        const int gi = (blockIdx.x + w * NB) * LPP + pg; // global point id
        const int b  = w;                                // batch == unroll index
                                                         // (w=0: gi<8192; w=1: gi>=8192)
        const float* en_i = s_en + sp * PAD;

        const float xi = __ldg(points + 3 * (size_t)gi);
        const float yi = __ldg(points + 3 * (size_t)gi + 1);
        const float zi = __ldg(points + 3 * (size_t)gi + 2);

        const int cx0 = max(0, (int)((xi - MARGIN) * INVC)), cx1 = min(GRIDC - 1, (int)((xi + MARGIN) * INVC));
        const int cy0 = max(0, (int)((yi - MARGIN) * INVC)), cy1 = min(GRIDC - 1, (int)((yi + MARGIN) * INVC));
        const int cz0 = max(0, (int)((zi - MARGIN) * INVC)), cz1 = min(GRIDC - 1, (int)((zi + MARGIN) * INVC));
        const int nx = cx1 - cx0 + 1, ny = cy1 - cy0 + 1, nz = cz1 - cz0 + 1;
        const int nxy = nx * ny, ncn = nxy * nz;         // <= 64 (a dim can straddle 4 cells)
        const float invnxy = 1.f / (float)nxy;
        const float invnx  = 1.f / (float)nx;

        const float* enb  = g_en + (size_t)b * NPTS * DIM;
        const float* embb = emb  + (size_t)b * NPTS * DIM;
        const unsigned char* cntb = s_cnt8 + b * NCELL;

        // ---- Phase A: geometric scan; defer passing j to candidate list.
        //      Common cells (cc=ln, cc=ln+16) prefetched together so both
        //      count-LDS latencies overlap; cc>=32 (~4% of points) stays serial ----
        {
            int cellA = 0, nA = 0, cellB = 0, nB = 0;
            if (ln < ncn) {
                int cc = ln;
                int cz = (int)(((float)cc + 0.5f) * invnxy);
                int r  = cc - cz * nxy;
                int cy = (int)(((float)r + 0.5f) * invnx);
                int cx = r - cy * nx;
                cellA = ((cz0 + cz) * GRIDC + (cy0 + cy)) * GRIDC + (cx0 + cx);
                nA = cntb[cellA];
            }
            if (ln + 16 < ncn) {
                int cc = ln + 16;
                int cz = (int)(((float)cc + 0.5f) * invnxy);
                int r  = cc - cz * nxy;
                int cy = (int)(((float)r + 0.5f) * invnx);
                int cx = r - cy * nx;
                cellB = ((cz0 + cz) * GRIDC + (cy0 + cy)) * GRIDC + (cx0 + cx);
                nB = cntb[cellB];
            }
#pragma unroll
            for (int pass = 0; pass < 2; pass++) {
                int cell = pass ? cellB : cellA;
                int n    = pass ? nB : nA;               // already clamped to CAP
                const float4* bk = g_bucket + ((size_t)b * NCELL + cell) * CAP;
                for (int k = 0; k < n; k++) {
                    float4 p = __ldg(bk + k);
                    float dx = xi - p.x, dy = yi - p.y, dz = zi - p.z;
                    float d2 = fmaf(dx, dx, fmaf(dy, dy, dz * dz));
                    if (d2 < R2) {                       // tiny divergent region
                        int pos = atomicAdd(&s_ccnt[sp], 1);
                        if (pos < CCAP) s_cand[sp * CCAP + pos] = __float_as_int(p.w);
                    }
                }
            }
            // rare tail: cc in [32, ncn)
            for (int s = 2; s < 4; s++) {
                int cc = ln + s * LPP;
                if (cc < ncn) {
                    int cz = (int)(((float)cc + 0.5f) * invnxy);
                    int r  = cc - cz * nxy;
                    int cy = (int)(((float)r + 0.5f) * invnx);
                    int cx = r - cy * nx;
                    int cell = ((cz0 + cz) * GRIDC + (cy0 + cy)) * GRIDC + (cx0 + cx);
                    int n = cntb[cell];
                    const float4* bk = g_bucket + ((size_t)b * NCELL + cell) * CAP;
                    for (int k = 0; k < n; k++) {
                        float4 p = __ldg(bk + k);
                        float dx = xi - p.x, dy = yi - p.y, dz = zi - p.z;
                        float d2 = fmaf(dx, dx, fmaf(dy, dy, dz * dz));
                        if (d2 < R2) {
                            int pos = atomicAdd(&s_ccnt[sp], 1);
                            if (pos < CCAP) s_cand[sp * CCAP + pos] = __float_as_int(p.w);
                        }
                    }
                }
            }
        }
        __syncwarp();                                    // candidate lists visible

        // ---- Phase B: dots computed cooperatively (full SIMT efficiency) ----
        const int nbcnt = s_ccnt[sp];                    // exact count (pre-clamp)
        const int mcand = min(nbcnt, CCAP);
        for (int i = ln; i < mcand; i += LPP) {          // lane takes candidate i
            int j = s_cand[sp * CCAP + i];
            const float4* ej = (const float4*)(enb + (size_t)j * DIM);
            float dot = 0.f;
#pragma unroll
            for (int q = 0; q < 8; q++) {
                float4 v = __ldg(ej + q);
                float4 u = *(const float4*)(en_i + 4 * q);   // broadcast LDS.128
                dot = fmaf(v.x, u.x, dot); dot = fmaf(v.y, u.y, dot);
                dot = fmaf(v.z, u.z, dot); dot = fmaf(v.w, u.w, dot);
            }
            if (dot > SIMT) {                            // rare: defer j
                int pos = atomicAdd(&s_lcnt[sp], 1);
                if (pos < LCAP) s_list[sp * LCAP + pos] = j;
            }
        }
        __syncwarp();                                    // sim lists visible

        const int cnt = s_lcnt[sp];                      // group-uniform
        const bool cond = (__ldg(leaf + gi) > 0) && (nbcnt > 1) && (cnt > 0)
                       && ((b == 0 ? lc0 : lc1) >= MINLEAF);

        const int ob = ln * 2;
        if (cond) {                                      // group-uniform branch
            const float rinv = 1.f / (float)cnt;         // cnt>0 here: == max(cnt,1)

            // cooperative accumulate: lane owns components {2ln, 2ln+1}
            float acc0 = 0.f, acc1 = 0.f;
            const int mm = min(cnt, LCAP);
            for (int i = 0; i < mm; i++) {
                int jj = s_list[sp * LCAP + i];          // broadcast LDS
                float2 v = *(const float2*)(embb + (size_t)jj * DIM + ob);  // 128B coalesced
                acc0 += v.x; acc1 += v.y;                // RAW embedding (exact)
            }
            const float cA = acc0 * rinv, cB = acc1 * rinv;

            float h0 = sb1[ob], h1 = sb1[ob + 1];
#pragma unroll 8
            for (int k = 0; k < DIM; k++) {
                float c = s_ei[sp * PAD + k];
                float2 wv = *(const float2*)(sW1 + k * DIM + ob);
                h0 = fmaf(c, wv.x, h0); h1 = fmaf(c, wv.y, h1);
            }
            // second half: acc broadcast via width-16 shfl, k ascending (same order)
#pragma unroll 8
            for (int k16 = 0; k16 < 16; k16++) {
                float c0 = __shfl_sync(gmask, cA, k16, 16);   // mean_sim[2*k16]
                float c1 = __shfl_sync(gmask, cB, k16, 16);   // mean_sim[2*k16+1]
                float2 w0 = *(const float2*)(sW1 + (DIM + 2 * k16) * DIM + ob);
                h0 = fmaf(c0, w0.x, h0); h1 = fmaf(c0, w0.y, h1);
                float2 w1 = *(const float2*)(sW1 + (DIM + 2 * k16 + 1) * DIM + ob);
                h0 = fmaf(c1, w1.x, h0); h1 = fmaf(c1, w1.y, h1);
            }
            h0 = fmaxf(h0, 0.f); h1 = fmaxf(h1, 0.f);

            // layer 2: h broadcast via width-16 shfl (group-converged: cond uniform)
            float o0 = sb2[ob], o1 = sb2[ob + 1];
#pragma unroll 8
            for (int k16 = 0; k16 < 16; k16++) {
                float c0 = __shfl_sync(gmask, h0, k16, 16);   // h[2*k16]
                float c1 = __shfl_sync(gmask, h1, k16, 16);   // h[2*k16+1]
                float2 w0 = *(const float2*)(sW2 + (2 * k16) * DIM + ob);
                o0 = fmaf(c0, w0.x, o0); o1 = fmaf(c0, w0.y, o1);
                float2 w1 = *(const float2*)(sW2 + (2 * k16 + 1) * DIM + ob);
                o0 = fmaf(c1, w1.x, o0); o1 = fmaf(c1, w1.y, o1);
            }
            *(float2*)(out + (size_t)gi * DIM + ob) = make_float2(o0, o1);
        } else {
            float2 r = *(const float2*)(s_ei + sp * PAD + ob);   // passthrough
            *(float2*)(out + (size_t)gi * DIM + ob) = r;
        }
        // no block sync: slots are per-point, staged once for both tiles
    }
}

extern "C" void kernel_launch(void* const* d_in, const int* in_sizes, int n_in,
                              void* d_out, int out_size) {
    const float* points = (const float*)d_in[0];
    const float* emb    = (const float*)d_in[1];
    const int*   leaf   = (const int*)d_in[2];
    const float* W1     = (const float*)d_in[3];
    const float* b1     = (const float*)d_in[4];
    const float* W2     = (const float*)d_in[5];
    const float* b2     = (const float*)d_in[6];
    float* out = (float*)d_out;

    fused_kernel<<<NB, TPB>>>(points, emb, leaf, W1, b1, W2, b2, out);
}